// round 16
// baseline (speedup 1.0000x reference)
#include <cuda_runtime.h>

// Pfaffian of 128x128 skew-symmetric submatrices gathered from a 256x256
// skew matrix F_full (strict lower tri F: F_full[i][j]=F[i(i-1)/2+j], i>j).
//
// One CTA / batch element. Parlett-Reid LTL^T, 2 steps per block, 32 blocks.
// ONE __syncthreads per iteration; deterministic skeleton:
//   threads 0-127:  snapshot(s+1) with REGISTER-APPLIED block-s correction of
//                   the few lines it reads (rows k+4,k+6; cols k+5,k+7 +
//                   scalars) -- same fma chain bulk would use => bit-exact.
//                   Those lines are DEAD afterward; never written to smem.
//   threads 128-639: apply block s to the live region: rows >= 4s+8,
//                   chunks >= s+2 (disjoint from all snapshot reads).
// Bit-exact vs XLA codegen (rel_err == 0.0 lineage):
//   tau = masked row_k * (1/pivot)  (one __fdiv_rn then __fmul_rn)
//   A'  = fma(-col_r, tau_c, fma(tau_r, col_c, A))  (contracted, step order)
//   pf  = sequential __fmul_rn of pivots

#define N128 128
#define LDA  132
#define NTHR 640
#define NC4  (N128 / 4)

extern __shared__ float smem[];

__device__ __forceinline__ float4 apply2_f4(float4 a, float t1r, float c1r,
                                            float t2r, float c2r,
                                            float4 t1v, float4 c1v,
                                            float4 t2v, float4 c2v)
{
    const float vx = __fmaf_rn(-c1r, t1v.x, __fmaf_rn(t1r, c1v.x, a.x));
    const float vy = __fmaf_rn(-c1r, t1v.y, __fmaf_rn(t1r, c1v.y, a.y));
    const float vz = __fmaf_rn(-c1r, t1v.z, __fmaf_rn(t1r, c1v.z, a.z));
    const float vw = __fmaf_rn(-c1r, t1v.w, __fmaf_rn(t1r, c1v.w, a.w));
    a.x = __fmaf_rn(-c2r, t2v.x, __fmaf_rn(t2r, c2v.x, vx));
    a.y = __fmaf_rn(-c2r, t2v.y, __fmaf_rn(t2r, c2v.y, vy));
    a.z = __fmaf_rn(-c2r, t2v.z, __fmaf_rn(t2r, c2v.z, vz));
    a.w = __fmaf_rn(-c2r, t2v.w, __fmaf_rn(t2r, c2v.w, vw));
    return a;
}

// Block correction of one element (r,c): exact fma chain of the rank-2 pair.
__device__ __forceinline__ float corr4(float a,
                                       float t1r, float c1r, float t2r, float c2r,
                                       float t1c, float c1c, float t2c, float c2c)
{
    const float v = __fmaf_rn(-c1r, t1c, __fmaf_rn(t1r, c1c, a));
    return __fmaf_rn(-c2r, t2c, __fmaf_rn(t2r, c2c, v));
}

// Plain snapshot for block 0 (no prior correction). Barrier-free: cross-thread
// scalars recomputed redundantly (bit-identical). Threads 0-127.
__device__ __forceinline__ void snapshot0(const float* __restrict__ A,
                                          float* __restrict__ tau1,
                                          float* __restrict__ col1,
                                          float* __restrict__ tau2,
                                          float* __restrict__ col2,
                                          int t, float& pf)
{
    const float pivot1 = A[0 * LDA + 1];
    const float invp1  = __fdiv_rn(1.0f, pivot1);
    const float akt    = A[0 * LDA + t];
    const float atk1   = A[t * LDA + 1];
    const float ak2t   = A[2 * LDA + t];
    const float atk3   = A[t * LDA + 3];
    const float ak2k3  = A[2 * LDA + 3];
    const float tk2 = __fmul_rn(A[0 * LDA + 2], invp1);
    const float tk3 = __fmul_rn(A[0 * LDA + 3], invp1);
    const float ck2 = A[2 * LDA + 1];
    const float ck3 = A[3 * LDA + 1];

    const float t1 = (t > 1) ? __fmul_rn(akt, invp1) : 0.0f;
    const float c1 = (t > 1) ? atk1 : 0.0f;
    tau1[t] = t1;
    col1[t] = c1;

    const float pivot2 = __fmaf_rn(-ck2, tk3, __fmaf_rn(tk2, ck3, ak2k3));
    const float invp2  = __fdiv_rn(1.0f, pivot2);
    const float row2    = __fmaf_rn(-ck2, t1, __fmaf_rn(tk2, c1, ak2t));
    const float col2raw = __fmaf_rn(-c1, tk3, __fmaf_rn(t1, ck3, atk3));
    tau2[t] = (t > 3) ? __fmul_rn(row2, invp2) : 0.0f;
    col2[t] = (t > 3) ? col2raw : 0.0f;
    if (t == 0) pf = __fmul_rn(__fmul_rn(pf, pivot1), pivot2);
}

// Snapshot for block at row k, reading A that holds blocks 0..(prev-1) on its
// lines and applying the previous block's correction IN REGISTERS via the
// ct1/cc1/ct2/cc2 coefficient arrays. Threads 0-127, barrier-free.
__device__ __forceinline__ void snapshot_corr(const float* __restrict__ A,
                                              int k,
                                              const float* __restrict__ ct1,
                                              const float* __restrict__ cc1,
                                              const float* __restrict__ ct2,
                                              const float* __restrict__ cc2,
                                              float* __restrict__ tau1,
                                              float* __restrict__ col1,
                                              float* __restrict__ tau2,
                                              float* __restrict__ col2,
                                              int t, float& pf)
{
    // correction coefficients (broadcast scalars + per-thread)
    const float T1t = ct1[t],     C1t = cc1[t],     T2t = ct2[t],     C2t = cc2[t];
    const float T1a = ct1[k],     C1a = cc1[k],     T2a = ct2[k],     C2a = cc2[k];
    const float T1b = ct1[k + 1], C1b = cc1[k + 1], T2b = ct2[k + 1], C2b = cc2[k + 1];
    const float T1c = ct1[k + 2], C1c = cc1[k + 2], T2c = ct2[k + 2], C2c = cc2[k + 2];
    const float T1d = ct1[k + 3], C1d = cc1[k + 3], T2d = ct2[k + 3], C2d = cc2[k + 3];

    // corrected elements (bit-identical to the smem update bulk would do)
    const float pivot1 = corr4(A[k * LDA + (k + 1)], T1a, C1a, T2a, C2a, T1b, C1b, T2b, C2b);
    const float akt    = corr4(A[k * LDA + t],       T1a, C1a, T2a, C2a, T1t, C1t, T2t, C2t);
    const float atk1   = corr4(A[t * LDA + (k + 1)], T1t, C1t, T2t, C2t, T1b, C1b, T2b, C2b);
    const float ak2t   = corr4(A[(k + 2) * LDA + t], T1c, C1c, T2c, C2c, T1t, C1t, T2t, C2t);
    const float atk3   = corr4(A[t * LDA + (k + 3)], T1t, C1t, T2t, C2t, T1d, C1d, T2d, C2d);
    const float ak2k3  = corr4(A[(k + 2) * LDA + (k + 3)], T1c, C1c, T2c, C2c, T1d, C1d, T2d, C2d);
    const float akk2   = corr4(A[k * LDA + (k + 2)], T1a, C1a, T2a, C2a, T1c, C1c, T2c, C2c);
    const float akk3   = corr4(A[k * LDA + (k + 3)], T1a, C1a, T2a, C2a, T1d, C1d, T2d, C2d);
    const float ck2    = corr4(A[(k + 2) * LDA + (k + 1)], T1c, C1c, T2c, C2c, T1b, C1b, T2b, C2b);
    const float ck3    = corr4(A[(k + 3) * LDA + (k + 1)], T1d, C1d, T2d, C2d, T1b, C1b, T2b, C2b);

    const float invp1 = __fdiv_rn(1.0f, pivot1);
    const float t1 = (t > k + 1) ? __fmul_rn(akt, invp1) : 0.0f;
    const float c1 = (t > k + 1) ? atk1 : 0.0f;
    tau1[t] = t1;
    col1[t] = c1;

    const float tk2 = __fmul_rn(akk2, invp1);
    const float tk3 = __fmul_rn(akk3, invp1);
    const float pivot2 = __fmaf_rn(-ck2, tk3, __fmaf_rn(tk2, ck3, ak2k3));
    const float invp2  = __fdiv_rn(1.0f, pivot2);
    const float row2    = __fmaf_rn(-ck2, t1, __fmaf_rn(tk2, c1, ak2t));
    const float col2raw = __fmaf_rn(-c1, tk3, __fmaf_rn(t1, ck3, atk3));
    tau2[t] = (t > k + 3) ? __fmul_rn(row2, invp2) : 0.0f;
    col2[t] = (t > k + 3) ? col2raw : 0.0f;
    if (t == 0) pf = __fmul_rn(__fmul_rn(pf, pivot1), pivot2);
}

__global__ __launch_bounds__(NTHR, 1)
void pfaffian_kernel(const float* __restrict__ x,
                     const float* __restrict__ F,
                     float* __restrict__ out)
{
    float* A    = smem;                          // 128*132
    float* bufs = A + N128 * LDA;                // 2 parities * 4 arrays * 128
    float* sx   = bufs + 2 * 4 * N128;           // 128
    int*   idx  = (int*)(sx + N128);             // 128

    const int b = blockIdx.x;
    const int t = threadIdx.x;

    // ---- load x row + occupancy ranks (threads 0-127) ----
    if (t < N128) sx[t] = x[b * N128 + t];
    __syncthreads();
    if (t < N128) {
        const bool mine = sx[t] > 0.0f;
        int cntBefore = 0, totPos = 0;
        #pragma unroll 8
        for (int l = 0; l < N128; ++l) {
            const bool p = sx[l] > 0.0f;
            totPos += p ? 1 : 0;
            if (l < t) cntBefore += p ? 1 : 0;
        }
        const int pos = mine ? cntBefore : (totPos + (t - cntBefore));
        idx[pos] = mine ? t : (N128 + t);
    }
    __syncthreads();

    // ---- gather A[rr][c] = F_full[idx[rr], idx[c]] (640 threads) ----
    {
        const int c    = t % N128;
        const int jj   = idx[c];
        const int jtri = jj * (jj - 1) / 2;
        for (int rr = t / N128; rr < N128; rr += NTHR / N128) {
            const int i = idx[rr];
            float v;
            if (i > jj)      v =  __ldg(&F[i * (i - 1) / 2 + jj]);
            else if (i < jj) v = -__ldg(&F[jtri + i]);
            else             v = 0.0f;
            A[rr * LDA + c] = v;
        }
    }
    __syncthreads();

    float pf = 1.0f;

    // ---- prologue: snapshot block 0 into parity 0 ----
    if (t < N128)
        snapshot0(A, bufs, bufs + 128, bufs + 256, bufs + 384, t, pf);

    // ---- 31 iterations: snapshot(s+1) (reg-corrected) || bulk(block s) ----
    for (int s = 0; s < 31; ++s) {
        __syncthreads();   // orders snapshot(s) bufs + bulk(s-1) writes
        const int k = 4 * s;
        float* cur = bufs + (s & 1) * 512;
        float* nxt = bufs + ((s + 1) & 1) * 512;
        float* tau1p = cur;       float* col1p = cur + 128;
        float* tau2p = cur + 256; float* col2p = cur + 384;

        if (t < N128) {
            // snapshot for block s+1; block-s correction applied in registers
            snapshot_corr(A, k + 4, tau1p, col1p, tau2p, col2p,
                          nxt, nxt + 128, nxt + 256, nxt + 384, t, pf);
        } else {
            // bulk: block s on live region rows >= k+8, chunks >= s+2,
            // fixed residue-class chunk ownership (c4 % 4 == q)
            const int u = t - N128;
            const int r = u & 127;
            const int q = u >> 7;      // 0..3
            if (r >= k + 8) {
                const float t1r = tau1p[r], c1r = col1p[r];
                const float t2r = tau2p[r], c2r = col2p[r];
                float4* __restrict__ Ar = (float4*)(A + r * LDA);
                const float4* __restrict__ T1 = (const float4*)tau1p;
                const float4* __restrict__ C1 = (const float4*)col1p;
                const float4* __restrict__ T2 = (const float4*)tau2p;
                const float4* __restrict__ C2 = (const float4*)col2p;
                const int d = s + 2;
                #pragma unroll 4
                for (int c4 = d + ((q - d) & 3); c4 < NC4; c4 += 4)
                    Ar[c4] = apply2_f4(Ar[c4], t1r, c1r, t2r, c2r,
                                       T1[c4], C1[c4], T2[c4], C2[c4]);
            }
        }
    }

    if (t == 0) out[b] = pf;
}

extern "C" void kernel_launch(void* const* d_in, const int* in_sizes, int n_in,
                              void* d_out, int out_size)
{
    const float* x = (const float*)d_in[0];   // (B, 128) fp32
    const float* F = (const float*)d_in[1];   // 256*255/2 fp32
    float* out = (float*)d_out;               // (B,) fp32

    const int B = in_sizes[0] / N128;

    // A (128*132) + double-buffered tau/col (1024) + sx (128) + idx (128)
    const size_t shmem = (size_t)(N128 * LDA + 2 * 4 * N128 + 2 * N128)
                         * sizeof(float);

    cudaFuncSetAttribute(pfaffian_kernel,
                         cudaFuncAttributeMaxDynamicSharedMemorySize,
                         (int)shmem);

    pfaffian_kernel<<<B, NTHR, shmem>>>(x, F, out);
}